// round 2
// baseline (speedup 1.0000x reference)
#include <cuda_runtime.h>
#include <cuda_fp16.h>

#define BATCH 64
#define NIN   2048
#define DIN   16
#define NOUT  32
#define DOUT  32
#define JD    (NOUT*DOUT)   // 1024

// Scratch (device globals — no allocation allowed)
__device__ __half2 g_uhat[(size_t)BATCH * NIN * (JD/2)];  // [b][i][jd/2], 268 MB
__device__ float   g_s[BATCH * JD];
__device__ float   g_vsum[BATCH * JD];

// ---------- packed f32x2 helpers (sm_103a) ----------
__device__ __forceinline__ unsigned long long pack2(float lo, float hi) {
    unsigned long long r;
    asm("mov.b64 %0, {%1, %2};" : "=l"(r) : "f"(lo), "f"(hi));
    return r;
}
__device__ __forceinline__ void unpack2(unsigned long long v, float& lo, float& hi) {
    asm("mov.b64 {%0, %1}, %2;" : "=f"(lo), "=f"(hi) : "l"(v));
}
__device__ __forceinline__ unsigned long long ffma2(unsigned long long a,
                                                    unsigned long long b,
                                                    unsigned long long c) {
    unsigned long long d;
    asm("fma.rn.f32x2 %0, %1, %2, %3;" : "=l"(d) : "l"(a), "l"(b), "l"(c));
    return d;
}
__device__ __forceinline__ unsigned long long fadd2(unsigned long long a,
                                                    unsigned long long b) {
    unsigned long long d;
    asm("add.rn.f32x2 %0, %1, %2;" : "=l"(d) : "l"(a), "l"(b));
    return d;
}

__global__ void kernelZero() {
    int t = blockIdx.x * 1024 + threadIdx.x;
    g_s[t] = 0.f;
    g_vsum[t] = 0.f;
}

// u_hat[b,i,jd] = sum_k W[i,jd,k] * x[b,i,k]; store fp16.
// One block per i. Thread t owns jd pair (2t, 2t+1); W rows packed into f32x2
// registers; x staged in smem as duplicated float2 so the inner loop is
// LDS.128 + FFMA2 only.
__global__ void __launch_bounds__(512) kernelU(const float* __restrict__ x,
                                               const float* __restrict__ W) {
    __shared__ float2 xs[BATCH * DIN];   // duplicated {xv,xv}, 8 KB
    const int i = blockIdx.x;
    const int t = threadIdx.x;

    for (int r = t; r < BATCH * DIN; r += 512) {
        int b = r >> 4, k = r & 15;
        float xv = x[(size_t)b * (NIN * DIN) + (size_t)i * DIN + k];
        xs[r] = make_float2(xv, xv);
    }

    // W rows for jd0 = 2t, jd1 = 2t+1 (16 floats each), packed per-k
    const float4* W4 = reinterpret_cast<const float4*>(W + (size_t)i * JD * DIN);
    float4 wa[4], wb[4];
#pragma unroll
    for (int q = 0; q < 4; q++) { wa[q] = W4[8 * t + q]; wb[q] = W4[8 * t + 4 + q]; }
    unsigned long long w2[DIN];
#pragma unroll
    for (int q = 0; q < 4; q++) {
        const float* pa = &wa[q].x;
        const float* pb = &wb[q].x;
#pragma unroll
        for (int r = 0; r < 4; r++) w2[4*q + r] = pack2(pa[r], pb[r]);
    }
    __syncthreads();

    __half2* outp = g_uhat + (size_t)i * (JD/2) + t;
#pragma unroll 2
    for (int b = 0; b < BATCH; b++) {
        const ulonglong2* xb = reinterpret_cast<const ulonglong2*>(xs + b * DIN);
        unsigned long long accA = 0ull, accB = 0ull;  // two chains (packed zeros == {0,0})
#pragma unroll
        for (int q = 0; q < 4; q++) {
            ulonglong2 p0 = xb[2*q];
            ulonglong2 p1 = xb[2*q + 1];
            accA = ffma2(w2[4*q + 0], p0.x, accA);
            accB = ffma2(w2[4*q + 1], p0.y, accB);
            accA = ffma2(w2[4*q + 2], p1.x, accA);
            accB = ffma2(w2[4*q + 3], p1.y, accB);
        }
        unsigned long long acc = fadd2(accA, accB);
        float a0, a1;
        unpack2(acc, a0, a1);
        outp[(size_t)b * NIN * (JD/2)] = __floats2half2_rn(a0, a1);
    }
}

// Iter-0: s0[b,jd] = sum_i u_hat[b,i,jd]  (uniform c folded in at squash via pre=1/32)
__global__ void __launch_bounds__(256) kernelR0() {
    const int b = blockIdx.x;
    const int chunk = blockIdx.y;         // 16 chunks of 128 i's
    const int t = threadIdx.x;            // owns half2 pair (2t, 2t+1) -> jd 4t..4t+3
    float a0 = 0.f, a1 = 0.f, a2 = 0.f, a3 = 0.f;
    const uint2* base = reinterpret_cast<const uint2*>(
        g_uhat + ((size_t)b * NIN + (size_t)chunk * 128) * (JD/2)) + t;
#pragma unroll 4
    for (int ii = 0; ii < 128; ii++) {
        uint2 u = base[(size_t)ii * 256];
        __half2 h0 = *reinterpret_cast<__half2*>(&u.x);
        __half2 h1 = *reinterpret_cast<__half2*>(&u.y);
        float2 f0 = __half22float2(h0);
        float2 f1 = __half22float2(h1);
        a0 += f0.x; a1 += f0.y; a2 += f1.x; a3 += f1.y;
    }
    atomicAdd(&g_s[b * JD + 4*t + 0], a0);
    atomicAdd(&g_s[b * JD + 4*t + 1], a1);
    atomicAdd(&g_s[b * JD + 4*t + 2], a2);
    atomicAdd(&g_s[b * JD + 4*t + 3], a3);
}

// v = squash(pre * s); vsum += v; s = 0; write v to out
__global__ void __launch_bounds__(1024) kernelSquash(float pre, float* __restrict__ vout) {
    const int b = blockIdx.x;
    const int t = threadIdx.x;            // t = jd; warp = one j (32 d's)
    float s = g_s[b * JD + t] * pre;
    float s2 = s * s;
#pragma unroll
    for (int off = 16; off; off >>= 1) s2 += __shfl_xor_sync(0xffffffffu, s2, off);
    float scale = (s2 / (1.f + s2 + 1e-9f)) * rsqrtf(s2 + 1e-9f);
    float v = s * scale;
    vout[b * JD + t]   = v;
    g_vsum[b * JD + t] += v;
    g_s[b * JD + t]    = 0.f;
}

// Routing iter (k>=1), warp-local: lane = output capsule j.
// logit[j] = u_hat[b,i,j,:]·vsum[b,j,:]; softmax over lanes via shuffles;
// acc[j,:] += c[j]*u_hat. Warp handles 32 i's; block (8 warps) reduces via
// smem, then one global atomic pass.
__global__ void __launch_bounds__(256, 2) kernelRoute() {
    const int b = blockIdx.x;
    const int chunk = blockIdx.y;         // 8 chunks of 256 i's
    const int w = threadIdx.x >> 5;
    const int j = threadIdx.x & 31;

    __shared__ float sblk[JD];
    for (int r = threadIdx.x; r < JD; r += 256) sblk[r] = 0.f;

    // vsum row for capsule j: 32 floats in registers
    float v[DOUT];
    const float4* vp = reinterpret_cast<const float4*>(g_vsum + b * JD + j * DOUT);
#pragma unroll
    for (int q = 0; q < 8; q++) {
        float4 f = vp[q];
        v[4*q+0] = f.x; v[4*q+1] = f.y; v[4*q+2] = f.z; v[4*q+3] = f.w;
    }
    __syncthreads();

    float acc[DOUT];
#pragma unroll
    for (int d = 0; d < DOUT; d++) acc[d] = 0.f;

    const int i0 = chunk * 256 + w * 32;
    for (int ii = 0; ii < 32; ii++) {
        const uint4* up = reinterpret_cast<const uint4*>(
            g_uhat + ((size_t)b * NIN + i0 + ii) * (JD/2));
        uint4 q0 = up[j*4 + 0];
        uint4 q1 = up[j*4 + 1];
        uint4 q2 = up[j*4 + 2];
        uint4 q3 = up[j*4 + 3];

        float u[DOUT];
        {
            const unsigned int rr[16] = {q0.x,q0.y,q0.z,q0.w, q1.x,q1.y,q1.z,q1.w,
                                         q2.x,q2.y,q2.z,q2.w, q3.x,q3.y,q3.z,q3.w};
#pragma unroll
            for (int q = 0; q < 16; q++) {
                __half2 h = *reinterpret_cast<const __half2*>(&rr[q]);
                float2 f = __half22float2(h);
                u[2*q]   = f.x;
                u[2*q+1] = f.y;
            }
        }

        float l = 0.f;
#pragma unroll
        for (int d = 0; d < DOUT; d++) l = fmaf(u[d], v[d], l);

        // warp softmax over j
        float m = l;
#pragma unroll
        for (int off = 16; off; off >>= 1) m = fmaxf(m, __shfl_xor_sync(0xffffffffu, m, off));
        float e = __expf(l - m);
        float se = e;
#pragma unroll
        for (int off = 16; off; off >>= 1) se += __shfl_xor_sync(0xffffffffu, se, off);
        float c = e / se;

#pragma unroll
        for (int d = 0; d < DOUT; d++) acc[d] = fmaf(c, u[d], acc[d]);
    }

    // warp -> block reduction in smem (spread addresses, conflict-free-ish)
#pragma unroll
    for (int d = 0; d < DOUT; d++) atomicAdd(&sblk[j * DOUT + d], acc[d]);
    __syncthreads();

    for (int r = threadIdx.x; r < JD; r += 256) atomicAdd(&g_s[b * JD + r], sblk[r]);
}

extern "C" void kernel_launch(void* const* d_in, const int* in_sizes, int n_in,
                              void* d_out, int out_size) {
    const float* x = (const float*)d_in[0];   // [64, 2048, 16]
    const float* W = (const float*)d_in[1];   // [1, 2048, 32, 32, 16]
    float* out = (float*)d_out;               // [64, 32, 32]

    kernelZero<<<64, 1024>>>();
    kernelU<<<2048, 512>>>(x, W);
    kernelR0<<<dim3(64, 16), 256>>>();
    kernelSquash<<<64, 1024>>>(1.f / 32.f, out);   // iter 0
    kernelRoute<<<dim3(64, 8), 256>>>();
    kernelSquash<<<64, 1024>>>(1.f, out);          // iter 1
    kernelRoute<<<dim3(64, 8), 256>>>();
    kernelSquash<<<64, 1024>>>(1.f, out);          // iter 2 (final v in d_out)
}

// round 3
// speedup vs baseline: 1.2599x; 1.2599x over previous
#include <cuda_runtime.h>
#include <cuda_fp16.h>

#define BATCH 64
#define NIN   2048
#define DIN   16
#define NOUT  32
#define DOUT  32
#define JD    (NOUT*DOUT)   // 1024

// Scratch (device globals — no allocation allowed)
__device__ __half2 g_uhat[(size_t)BATCH * NIN * (JD/2)];  // [b][i][jd/2], 268 MB
__device__ float   g_s[BATCH * JD];
__device__ float   g_vsum[BATCH * JD];

// ---------- packed f32x2 helpers (sm_103a) ----------
__device__ __forceinline__ unsigned long long pack2(float lo, float hi) {
    unsigned long long r;
    asm("mov.b64 %0, {%1, %2};" : "=l"(r) : "f"(lo), "f"(hi));
    return r;
}
__device__ __forceinline__ void unpack2(unsigned long long v, float& lo, float& hi) {
    asm("mov.b64 {%0, %1}, %2;" : "=f"(lo), "=f"(hi) : "l"(v));
}
__device__ __forceinline__ unsigned long long ffma2(unsigned long long a,
                                                    unsigned long long b,
                                                    unsigned long long c) {
    unsigned long long d;
    asm("fma.rn.f32x2 %0, %1, %2, %3;" : "=l"(d) : "l"(a), "l"(b), "l"(c));
    return d;
}
__device__ __forceinline__ unsigned long long fadd2(unsigned long long a,
                                                    unsigned long long b) {
    unsigned long long d;
    asm("add.rn.f32x2 %0, %1, %2;" : "=l"(d) : "l"(a), "l"(b));
    return d;
}

// No-op launches: shift the ncu -s 5 -c 1 capture window onto kernelU.
__global__ void kernelNop() {}

__global__ void kernelZero() {
    int t = blockIdx.x * 1024 + threadIdx.x;
    g_s[t] = 0.f;
    g_vsum[t] = 0.f;
}

// u_hat[b,i,jd] = sum_k W[i,jd,k] * x[b,i,k]; store fp16.
// One block per i. Thread t owns jd pair (2t, 2t+1); W rows packed into f32x2
// registers; x staged in smem as duplicated float2 so the inner loop is
// LDS.128 + FFMA2 only.
__global__ void __launch_bounds__(512) kernelU(const float* __restrict__ x,
                                               const float* __restrict__ W) {
    __shared__ float2 xs[BATCH * DIN];   // duplicated {xv,xv}, 8 KB
    const int i = blockIdx.x;
    const int t = threadIdx.x;

    for (int r = t; r < BATCH * DIN; r += 512) {
        int b = r >> 4, k = r & 15;
        float xv = x[(size_t)b * (NIN * DIN) + (size_t)i * DIN + k];
        xs[r] = make_float2(xv, xv);
    }

    // W rows for jd0 = 2t, jd1 = 2t+1 (16 floats each), packed per-k
    const float4* W4 = reinterpret_cast<const float4*>(W + (size_t)i * JD * DIN);
    float4 wa[4], wb[4];
#pragma unroll
    for (int q = 0; q < 4; q++) { wa[q] = W4[8 * t + q]; wb[q] = W4[8 * t + 4 + q]; }
    unsigned long long w2[DIN];
#pragma unroll
    for (int q = 0; q < 4; q++) {
        const float* pa = &wa[q].x;
        const float* pb = &wb[q].x;
#pragma unroll
        for (int r = 0; r < 4; r++) w2[4*q + r] = pack2(pa[r], pb[r]);
    }
    __syncthreads();

    __half2* outp = g_uhat + (size_t)i * (JD/2) + t;
#pragma unroll 2
    for (int b = 0; b < BATCH; b++) {
        const ulonglong2* xb = reinterpret_cast<const ulonglong2*>(xs + b * DIN);
        unsigned long long accA = 0ull, accB = 0ull;  // two chains
#pragma unroll
        for (int q = 0; q < 4; q++) {
            ulonglong2 p0 = xb[2*q];
            ulonglong2 p1 = xb[2*q + 1];
            accA = ffma2(w2[4*q + 0], p0.x, accA);
            accB = ffma2(w2[4*q + 1], p0.y, accB);
            accA = ffma2(w2[4*q + 2], p1.x, accA);
            accB = ffma2(w2[4*q + 3], p1.y, accB);
        }
        unsigned long long acc = fadd2(accA, accB);
        float a0, a1;
        unpack2(acc, a0, a1);
        outp[(size_t)b * NIN * (JD/2)] = __floats2half2_rn(a0, a1);
    }
}

// Iter-0: s0[b,jd] = sum_i u_hat[b,i,jd]  (uniform c folded in at squash via pre=1/32)
__global__ void __launch_bounds__(256) kernelR0() {
    const int b = blockIdx.x;
    const int chunk = blockIdx.y;         // 16 chunks of 128 i's
    const int t = threadIdx.x;            // owns half2 pair (2t, 2t+1) -> jd 4t..4t+3
    float a0 = 0.f, a1 = 0.f, a2 = 0.f, a3 = 0.f;
    const uint2* base = reinterpret_cast<const uint2*>(
        g_uhat + ((size_t)b * NIN + (size_t)chunk * 128) * (JD/2)) + t;
#pragma unroll 4
    for (int ii = 0; ii < 128; ii++) {
        uint2 u = base[(size_t)ii * 256];
        __half2 h0 = *reinterpret_cast<__half2*>(&u.x);
        __half2 h1 = *reinterpret_cast<__half2*>(&u.y);
        float2 f0 = __half22float2(h0);
        float2 f1 = __half22float2(h1);
        a0 += f0.x; a1 += f0.y; a2 += f1.x; a3 += f1.y;
    }
    atomicAdd(&g_s[b * JD + 4*t + 0], a0);
    atomicAdd(&g_s[b * JD + 4*t + 1], a1);
    atomicAdd(&g_s[b * JD + 4*t + 2], a2);
    atomicAdd(&g_s[b * JD + 4*t + 3], a3);
}

// v = squash(pre * s); vsum += v; s = 0; write v to out
__global__ void __launch_bounds__(1024) kernelSquash(float pre, float* __restrict__ vout) {
    const int b = blockIdx.x;
    const int t = threadIdx.x;            // t = jd; warp = one j (32 d's)
    float s = g_s[b * JD + t] * pre;
    float s2 = s * s;
#pragma unroll
    for (int off = 16; off; off >>= 1) s2 += __shfl_xor_sync(0xffffffffu, s2, off);
    float scale = (s2 / (1.f + s2 + 1e-9f)) * rsqrtf(s2 + 1e-9f);
    float v = s * scale;
    vout[b * JD + t]   = v;
    g_vsum[b * JD + t] += v;
    g_s[b * JD + t]    = 0.f;
}

// Routing iter (k>=1), warp-local: lane = output capsule j.
// u/v/acc all held as packed f32x2 (16 ulonglong each) -> ~116 regs, no spills.
// Zero block barriers in the inner loop; warp->block reduction via
// xor-swizzled conflict-free STS, then one atomic pass.
__global__ void __launch_bounds__(128) kernelRoute() {
    const int b = blockIdx.x;
    const int chunk = blockIdx.y;         // 16 chunks of 128 i's
    const int w = threadIdx.x >> 5;       // warp 0..3
    const int j = threadIdx.x & 31;       // lane = output capsule

    __shared__ float sred[4][JD];         // 16 KB per-warp partials

    // vsum row for capsule j, packed f32x2
    unsigned long long v2[16];
    {
        const float4* vp = reinterpret_cast<const float4*>(g_vsum + b * JD + j * DOUT);
#pragma unroll
        for (int q = 0; q < 8; q++) {
            float4 f = vp[q];
            v2[2*q]   = pack2(f.x, f.y);
            v2[2*q+1] = pack2(f.z, f.w);
        }
    }

    unsigned long long acc2[16];
#pragma unroll
    for (int q = 0; q < 16; q++) acc2[q] = 0ull;

    const int i0 = chunk * 128 + w * 32;
    for (int ii = 0; ii < 32; ii++) {
        const uint4* up = reinterpret_cast<const uint4*>(
            g_uhat + ((size_t)b * NIN + i0 + ii) * (JD/2));
        uint4 qq[4];
        qq[0] = up[j*4 + 0];
        qq[1] = up[j*4 + 1];
        qq[2] = up[j*4 + 2];
        qq[3] = up[j*4 + 3];

        // convert 16 half2 -> 16 packed f32x2
        unsigned long long u2[16];
#pragma unroll
        for (int q = 0; q < 4; q++) {
            const unsigned int* rr = &qq[q].x;
#pragma unroll
            for (int r = 0; r < 4; r++) {
                float2 f = __half22float2(*reinterpret_cast<const __half2*>(&rr[r]));
                u2[4*q + r] = pack2(f.x, f.y);
            }
        }

        // logit = u . v  (packed FMA, two chains)
        unsigned long long lA = 0ull, lB = 0ull;
#pragma unroll
        for (int q = 0; q < 8; q++) {
            lA = ffma2(u2[2*q],   v2[2*q],   lA);
            lB = ffma2(u2[2*q+1], v2[2*q+1], lB);
        }
        float l0, l1;
        unpack2(fadd2(lA, lB), l0, l1);
        float l = l0 + l1;

        // warp softmax over j
        float m = l;
#pragma unroll
        for (int off = 16; off; off >>= 1) m = fmaxf(m, __shfl_xor_sync(0xffffffffu, m, off));
        float e = __expf(l - m);
        float se = e;
#pragma unroll
        for (int off = 16; off; off >>= 1) se += __shfl_xor_sync(0xffffffffu, se, off);
        float c = e / se;
        unsigned long long c2 = pack2(c, c);

#pragma unroll
        for (int q = 0; q < 16; q++) acc2[q] = ffma2(u2[q], c2, acc2[q]);
    }

    // per-warp partials, xor-swizzled so lanes hit distinct banks per d
#pragma unroll
    for (int q = 0; q < 16; q++) {
        float a0, a1;
        unpack2(acc2[q], a0, a1);
        int d0 = 2*q, d1 = 2*q + 1;
        sred[w][j * DOUT + (d0 ^ j)] = a0;
        sred[w][j * DOUT + (d1 ^ j)] = a1;
    }
    __syncthreads();

    for (int r = threadIdx.x; r < JD; r += 128) {
        int jj = r >> 5, dd = r & 31;
        int d = dd ^ jj;                  // unswizzle
        float sum = sred[0][r] + sred[1][r] + sred[2][r] + sred[3][r];
        atomicAdd(&g_s[b * JD + jj * DOUT + d], sum);
    }
}

extern "C" void kernel_launch(void* const* d_in, const int* in_sizes, int n_in,
                              void* d_out, int out_size) {
    const float* x = (const float*)d_in[0];   // [64, 2048, 16]
    const float* W = (const float*)d_in[1];   // [1, 2048, 32, 32, 16]
    float* out = (float*)d_out;               // [64, 32, 32]

    // 4 no-ops: ncu (-s 5 -c 1) then captures kernelU (launch #6)
    kernelNop<<<1, 32>>>();
    kernelNop<<<1, 32>>>();
    kernelNop<<<1, 32>>>();
    kernelNop<<<1, 32>>>();

    kernelZero<<<64, 1024>>>();
    kernelU<<<2048, 512>>>(x, W);
    kernelR0<<<dim3(64, 16), 256>>>();
    kernelSquash<<<64, 1024>>>(1.f / 32.f, out);   // iter 0
    kernelRoute<<<dim3(64, 16), 128>>>();
    kernelSquash<<<64, 1024>>>(1.f, out);          // iter 1
    kernelRoute<<<dim3(64, 16), 128>>>();
    kernelSquash<<<64, 1024>>>(1.f, out);          // iter 2 (final v in d_out)
}

// round 4
// speedup vs baseline: 1.4479x; 1.1492x over previous
#include <cuda_runtime.h>
#include <cuda_fp16.h>

#define BATCH 64
#define NIN   2048
#define DIN   16
#define NOUT  32
#define DOUT  32
#define JD    (NOUT*DOUT)   // 1024

// Scratch (device globals — no allocation allowed)
__device__ __half2 g_uhat[(size_t)BATCH * NIN * (JD/2)];  // [b][i][jd/2], 268 MB
__device__ float   g_s[BATCH * JD];
__device__ float   g_vsum[BATCH * JD];

// ---------- packed f32x2 helpers (sm_103a) ----------
__device__ __forceinline__ unsigned long long pack2(float lo, float hi) {
    unsigned long long r;
    asm("mov.b64 %0, {%1, %2};" : "=l"(r) : "f"(lo), "f"(hi));
    return r;
}
__device__ __forceinline__ void unpack2(unsigned long long v, float& lo, float& hi) {
    asm("mov.b64 {%0, %1}, %2;" : "=f"(lo), "=f"(hi) : "l"(v));
}
__device__ __forceinline__ unsigned long long ffma2(unsigned long long a,
                                                    unsigned long long b,
                                                    unsigned long long c) {
    unsigned long long d;
    asm("fma.rn.f32x2 %0, %1, %2, %3;" : "=l"(d) : "l"(a), "l"(b), "l"(c));
    return d;
}
__device__ __forceinline__ unsigned long long fadd2(unsigned long long a,
                                                    unsigned long long b) {
    unsigned long long d;
    asm("add.rn.f32x2 %0, %1, %2;" : "=l"(d) : "l"(a), "l"(b));
    return d;
}

__global__ void kernelZero() {
    int t = blockIdx.x * 1024 + threadIdx.x;
    g_s[t] = 0.f;
    g_vsum[t] = 0.f;
}

// u_hat[b,i,jd] = sum_k W[i,jd,k] * x[b,i,k]; store fp16.
// One block per i. Thread t owns jd pair (2t, 2t+1); W rows packed into f32x2
// registers. x staged in smem as plain float4 — inner loop reads it with
// warp-BROADCAST LDS.128 (all lanes same address -> conflict-free, 1 phase),
// cutting smem crossbar traffic 8x vs the duplicated-float2 version.
__global__ void __launch_bounds__(512) kernelU(const float* __restrict__ x,
                                               const float* __restrict__ W) {
    __shared__ float4 xs[BATCH * 4];     // [b][quarter], 4 KB
    const int i = blockIdx.x;
    const int t = threadIdx.x;

    if (t < BATCH * 4) {
        int b = t >> 2, q = t & 3;
        xs[t] = reinterpret_cast<const float4*>(
                    x + (size_t)b * (NIN * DIN) + (size_t)i * DIN)[q];
    }

    // W rows for jd0 = 2t, jd1 = 2t+1 (16 floats each), packed per-k
    const float4* W4 = reinterpret_cast<const float4*>(W + (size_t)i * JD * DIN);
    float4 wa[4], wb[4];
#pragma unroll
    for (int q = 0; q < 4; q++) { wa[q] = W4[8 * t + q]; wb[q] = W4[8 * t + 4 + q]; }
    unsigned long long w2[DIN];
#pragma unroll
    for (int q = 0; q < 4; q++) {
        const float* pa = &wa[q].x;
        const float* pb = &wb[q].x;
#pragma unroll
        for (int r = 0; r < 4; r++) w2[4*q + r] = pack2(pa[r], pb[r]);
    }
    __syncthreads();

    __half2* outp = g_uhat + (size_t)i * (JD/2) + t;
#pragma unroll 2
    for (int b = 0; b < BATCH; b++) {
        const float4* xb = xs + b * 4;
        unsigned long long accA = 0ull, accB = 0ull;  // two chains
#pragma unroll
        for (int q = 0; q < 4; q++) {
            float4 f = xb[q];             // broadcast LDS.128
            accA = ffma2(w2[4*q + 0], pack2(f.x, f.x), accA);
            accB = ffma2(w2[4*q + 1], pack2(f.y, f.y), accB);
            accA = ffma2(w2[4*q + 2], pack2(f.z, f.z), accA);
            accB = ffma2(w2[4*q + 3], pack2(f.w, f.w), accB);
        }
        unsigned long long acc = fadd2(accA, accB);
        float a0, a1;
        unpack2(acc, a0, a1);
        outp[(size_t)b * NIN * (JD/2)] = __floats2half2_rn(a0, a1);
    }
}

// Iter-0: s0[b,jd] = sum_i u_hat[b,i,jd]  (uniform c folded in at squash via pre=1/32)
__global__ void __launch_bounds__(256) kernelR0() {
    const int b = blockIdx.x;
    const int chunk = blockIdx.y;         // 16 chunks of 128 i's
    const int t = threadIdx.x;            // owns half2 pair (2t, 2t+1) -> jd 4t..4t+3
    float a0 = 0.f, a1 = 0.f, a2 = 0.f, a3 = 0.f;
    const uint2* base = reinterpret_cast<const uint2*>(
        g_uhat + ((size_t)b * NIN + (size_t)chunk * 128) * (JD/2)) + t;
#pragma unroll 4
    for (int ii = 0; ii < 128; ii++) {
        uint2 u = base[(size_t)ii * 256];
        __half2 h0 = *reinterpret_cast<__half2*>(&u.x);
        __half2 h1 = *reinterpret_cast<__half2*>(&u.y);
        float2 f0 = __half22float2(h0);
        float2 f1 = __half22float2(h1);
        a0 += f0.x; a1 += f0.y; a2 += f1.x; a3 += f1.y;
    }
    atomicAdd(&g_s[b * JD + 4*t + 0], a0);
    atomicAdd(&g_s[b * JD + 4*t + 1], a1);
    atomicAdd(&g_s[b * JD + 4*t + 2], a2);
    atomicAdd(&g_s[b * JD + 4*t + 3], a3);
}

// v = squash(pre * s); vsum += v; s = 0; write v to out
__global__ void __launch_bounds__(1024) kernelSquash(float pre, float* __restrict__ vout) {
    const int b = blockIdx.x;
    const int t = threadIdx.x;            // t = jd; warp = one j (32 d's)
    float s = g_s[b * JD + t] * pre;
    float s2 = s * s;
#pragma unroll
    for (int off = 16; off; off >>= 1) s2 += __shfl_xor_sync(0xffffffffu, s2, off);
    float scale = (s2 / (1.f + s2 + 1e-9f)) * rsqrtf(s2 + 1e-9f);
    float v = s * scale;
    vout[b * JD + t]   = v;
    g_vsum[b * JD + t] += v;
    g_s[b * JD + t]    = 0.f;
}

// Routing iter (k>=1), warp-local: lane = output capsule j.
// u/v/acc all held as packed f32x2 -> no spills. Zero block barriers in the
// inner loop; warp->block reduction via xor-swizzled conflict-free STS,
// then one atomic pass.
__global__ void __launch_bounds__(128) kernelRoute() {
    const int b = blockIdx.x;
    const int chunk = blockIdx.y;         // 16 chunks of 128 i's
    const int w = threadIdx.x >> 5;       // warp 0..3
    const int j = threadIdx.x & 31;       // lane = output capsule

    __shared__ float sred[4][JD];         // 16 KB per-warp partials

    // vsum row for capsule j, packed f32x2
    unsigned long long v2[16];
    {
        const float4* vp = reinterpret_cast<const float4*>(g_vsum + b * JD + j * DOUT);
#pragma unroll
        for (int q = 0; q < 8; q++) {
            float4 f = vp[q];
            v2[2*q]   = pack2(f.x, f.y);
            v2[2*q+1] = pack2(f.z, f.w);
        }
    }

    unsigned long long acc2[16];
#pragma unroll
    for (int q = 0; q < 16; q++) acc2[q] = 0ull;

    const int i0 = chunk * 128 + w * 32;
    for (int ii = 0; ii < 32; ii++) {
        const uint4* up = reinterpret_cast<const uint4*>(
            g_uhat + ((size_t)b * NIN + i0 + ii) * (JD/2));
        uint4 qq[4];
        qq[0] = up[j*4 + 0];
        qq[1] = up[j*4 + 1];
        qq[2] = up[j*4 + 2];
        qq[3] = up[j*4 + 3];

        // convert 16 half2 -> 16 packed f32x2
        unsigned long long u2[16];
#pragma unroll
        for (int q = 0; q < 4; q++) {
            const unsigned int* rr = &qq[q].x;
#pragma unroll
            for (int r = 0; r < 4; r++) {
                float2 f = __half22float2(*reinterpret_cast<const __half2*>(&rr[r]));
                u2[4*q + r] = pack2(f.x, f.y);
            }
        }

        // logit = u . v  (packed FMA, two chains)
        unsigned long long lA = 0ull, lB = 0ull;
#pragma unroll
        for (int q = 0; q < 8; q++) {
            lA = ffma2(u2[2*q],   v2[2*q],   lA);
            lB = ffma2(u2[2*q+1], v2[2*q+1], lB);
        }
        float l0, l1;
        unpack2(fadd2(lA, lB), l0, l1);
        float l = l0 + l1;

        // warp softmax over j
        float m = l;
#pragma unroll
        for (int off = 16; off; off >>= 1) m = fmaxf(m, __shfl_xor_sync(0xffffffffu, m, off));
        float e = __expf(l - m);
        float se = e;
#pragma unroll
        for (int off = 16; off; off >>= 1) se += __shfl_xor_sync(0xffffffffu, se, off);
        float c = e / se;
        unsigned long long c2 = pack2(c, c);

#pragma unroll
        for (int q = 0; q < 16; q++) acc2[q] = ffma2(u2[q], c2, acc2[q]);
    }

    // per-warp partials, xor-swizzled so lanes hit distinct banks per d
#pragma unroll
    for (int q = 0; q < 16; q++) {
        float a0, a1;
        unpack2(acc2[q], a0, a1);
        int d0 = 2*q, d1 = 2*q + 1;
        sred[w][j * DOUT + (d0 ^ j)] = a0;
        sred[w][j * DOUT + (d1 ^ j)] = a1;
    }
    __syncthreads();

    for (int r = threadIdx.x; r < JD; r += 128) {
        int jj = r >> 5, dd = r & 31;
        int d = dd ^ jj;                  // unswizzle
        float sum = sred[0][r] + sred[1][r] + sred[2][r] + sred[3][r];
        atomicAdd(&g_s[b * JD + jj * DOUT + d], sum);
    }
}

extern "C" void kernel_launch(void* const* d_in, const int* in_sizes, int n_in,
                              void* d_out, int out_size) {
    const float* x = (const float*)d_in[0];   // [64, 2048, 16]
    const float* W = (const float*)d_in[1];   // [1, 2048, 32, 32, 16]
    float* out = (float*)d_out;               // [64, 32, 32]

    kernelZero<<<64, 1024>>>();
    kernelU<<<2048, 512>>>(x, W);
    kernelR0<<<dim3(64, 16), 256>>>();
    kernelSquash<<<64, 1024>>>(1.f / 32.f, out);   // iter 0
    kernelRoute<<<dim3(64, 16), 128>>>();
    kernelSquash<<<64, 1024>>>(1.f, out);          // iter 1
    kernelRoute<<<dim3(64, 16), 128>>>();
    kernelSquash<<<64, 1024>>>(1.f, out);          // iter 2 (final v in d_out)
}